// round 10
// baseline (speedup 1.0000x reference)
#include <cuda_runtime.h>
#include <cuda_bf16.h>
#include <cstdint>

// ---------------------------------------------------------------------------
// TimeAwareRNN  (L=256, B=512, K_IN=15, K_STATE=512, K_OUT=8, MEANDT=1)
//
// Python precedence: r * h @ Wlin.T == (r * h) @ Wlin.T, so each RK stage is
// two DEPENDENT GEMMs:
//   (A) G = hs @ Wg^T   -> z = sig(Gz+lxz+bgz), rh = sig(Gr+lxr+bgr)*hs
//   (B) M = rh @ Wlin^T -> k = z*(tanh(lxl+M+blin)-hs), RK4 update
//
// Phases:
//   1. xe  = tanh(x @ Win^T + bin)                      (L*B, 512)
//   2. Lx  = xe @ Wx^T                                  (L*B, 1536)
//   3. RK4 scan: ONE persistent kernel (128 blocks, 1/SM guaranteed
//      co-resident), weight slices resident in smem (192KB/block),
//      software grid barrier between dependent GEMMs (2048 barriers).
//   4. T = tanh(states[0:255] @ Ly1^T); y = T @ Ly2^T -> out rows 1..255
//      out row 0 = Ly(h0)
// ---------------------------------------------------------------------------

#define LSEQ   256
#define BDIM   512
#define KS     512
#define KIN    15
#define KOUT   8
#define NWX    1536
#define LB     (LSEQ * BDIM)          // 131072
#define NB     128                    // scan grid (<= 148 SMs, 1 block/SM)

// ------------------------------- scratch -----------------------------------
__device__ float g_xe[(size_t)LB * KS];        // 268 MB (reused as T)
__device__ float g_Lx[(size_t)LB * NWX];       // 805 MB
__device__ float g_states[(size_t)LB * KS];    // 268 MB
__device__ float g_hsbuf[2][BDIM * KS];        // ping-pong stage states
__device__ float g_rh[BDIM * KS];              // r*hs exchange buffer
__device__ unsigned g_barcnt = 0;              // monotonic barrier counter

// ------------------------------- helpers -----------------------------------
__device__ __forceinline__ float sigmoidf_(float x) {
    return __fdividef(1.0f, 1.0f + __expf(-x));
}

// Replay-safe monotonic grid barrier. EVERY thread fences first so its own
// global stores are device-visible before arrival (syncthreads alone only
// gives block-scope visibility; a fence by thread 0 alone would order only
// thread 0's accesses). Then one ticket per block; counter is a multiple of
// NB at each barrier boundary; release target = next multiple above the
// ticket. Counter never resets -> safe across graph replays; signed
// difference handles u32 wrap.
__device__ __forceinline__ void grid_barrier() {
    __threadfence();                  // release: all threads' prior STG -> L2
    __syncthreads();                  // all fences done before leader arrives
    if (threadIdx.x == 0) {
        unsigned my = atomicAdd(&g_barcnt, 1u);
        unsigned target = my - (my % NB) + NB;
        while ((int)(*(volatile unsigned*)&g_barcnt - target) < 0)
            __nanosleep(32);
        __threadfence();              // acquire on the leader
    }
    __syncthreads();                  // block waits on leader
}

// --------------------------- init hs = state0 ------------------------------
__global__ void init_kernel(const float* __restrict__ state0) {
    int idx = blockIdx.x * blockDim.x + threadIdx.x;   // 512*512 total
    g_hsbuf[0][idx] = state0[idx & (KS - 1)];
}

// ------------------------- y0 = Ly(h0) -> out[0] ---------------------------
__global__ void y0_kernel(const float* __restrict__ state0,
                          const float* __restrict__ Ly1,
                          const float* __restrict__ Ly2,
                          float* __restrict__ out) {
    __shared__ float t0[KS];
    __shared__ float y0s[KOUT];
    int tid = threadIdx.x;            // 512 threads, 16 warps
    int lane = tid & 31, w = tid >> 5;
    for (int jj = 0; jj < 32; ++jj) {
        int j = w * 32 + jj;
        float s = 0.f;
        #pragma unroll 4
        for (int c = 0; c < 16; ++c)
            s += state0[lane * 16 + c] * Ly1[j * KS + lane * 16 + c];
        #pragma unroll
        for (int sh = 16; sh; sh >>= 1) s += __shfl_xor_sync(0xffffffffu, s, sh);
        if (lane == 0) t0[j] = tanhf(s);
    }
    __syncthreads();
    if (w < KOUT) {
        float s = 0.f;
        #pragma unroll 4
        for (int c = 0; c < 16; ++c)
            s += t0[lane * 16 + c] * Ly2[w * KS + lane * 16 + c];
        #pragma unroll
        for (int sh = 16; sh; sh >>= 1) s += __shfl_xor_sync(0xffffffffu, s, sh);
        if (lane == 0) y0s[w] = s;
    }
    __syncthreads();
    for (int u = tid; u < BDIM * KOUT; u += blockDim.x)
        out[u] = y0s[u & (KOUT - 1)];
}

// ------------------------ xe = tanh(x @ Win^T + bin) -----------------------
__global__ __launch_bounds__(256)
void xe_kernel(const float* __restrict__ seq,
               const float* __restrict__ Win,
               const float* __restrict__ bin) {
    __shared__ float sW[KS * KIN];    // 30 KB
    __shared__ float sb[KS];
    __shared__ float sx[4][16];
    int tid = threadIdx.x;
    for (int u = tid; u < KS * KIN; u += 256) sW[u] = Win[u];
    for (int u = tid; u < KS; u += 256) sb[u] = bin[u];
    int r0 = blockIdx.x * 4;
    if (tid < 64) sx[tid >> 4][tid & 15] = seq[(size_t)(r0 + (tid >> 4)) * 16 + (tid & 15)];
    __syncthreads();
    #pragma unroll
    for (int r = 0; r < 4; ++r) {
        #pragma unroll
        for (int jj = 0; jj < 2; ++jj) {
            int j = jj * 256 + tid;
            float s = sb[j];
            #pragma unroll
            for (int k = 0; k < KIN; ++k) s = fmaf(sx[r][k], sW[j * KIN + k], s);
            g_xe[(size_t)(r0 + r) * KS + j] = tanhf(s);
        }
    }
}

// --------- generic NT SGEMM: C[m,n] = sum_k A[m,k]*B[n,k] (opt tanh) -------
// BM=BN=128, BK=16, 256 threads, 8x8 microtile.  M%128==0, N%128==0, K%16==0
template<bool TANH>
__global__ __launch_bounds__(256)
void sgemm_nt(const float* __restrict__ A, const float* __restrict__ Bm,
              float* __restrict__ C, int M, int N, int K) {
    __shared__ float As[16][132];
    __shared__ float Bs[16][132];
    const int tid = threadIdx.x;
    const int tx = tid & 15, ty = tid >> 4;
    const int bn0 = blockIdx.x * 128;
    const int bm0 = blockIdx.y * 128;
    const int lm = tid >> 2;              // 0..63
    const int lk = (tid & 3) * 4;         // 0,4,8,12
    float acc[8][8];
    #pragma unroll
    for (int i = 0; i < 8; ++i)
        #pragma unroll
        for (int j = 0; j < 8; ++j) acc[i][j] = 0.f;

    const float* Ap  = A  + (size_t)(bm0 + lm) * K + lk;
    const float* Ap2 = Ap + (size_t)64 * K;
    const float* Bp  = Bm + (size_t)(bn0 + lm) * K + lk;
    const float* Bp2 = Bp + (size_t)64 * K;

    for (int k0 = 0; k0 < K; k0 += 16) {
        float4 a0 = *(const float4*)(Ap  + k0);
        float4 a1 = *(const float4*)(Ap2 + k0);
        float4 b0 = *(const float4*)(Bp  + k0);
        float4 b1 = *(const float4*)(Bp2 + k0);
        As[lk + 0][lm] = a0.x; As[lk + 1][lm] = a0.y;
        As[lk + 2][lm] = a0.z; As[lk + 3][lm] = a0.w;
        As[lk + 0][lm + 64] = a1.x; As[lk + 1][lm + 64] = a1.y;
        As[lk + 2][lm + 64] = a1.z; As[lk + 3][lm + 64] = a1.w;
        Bs[lk + 0][lm] = b0.x; Bs[lk + 1][lm] = b0.y;
        Bs[lk + 2][lm] = b0.z; Bs[lk + 3][lm] = b0.w;
        Bs[lk + 0][lm + 64] = b1.x; Bs[lk + 1][lm + 64] = b1.y;
        Bs[lk + 2][lm + 64] = b1.z; Bs[lk + 3][lm + 64] = b1.w;
        __syncthreads();
        #pragma unroll
        for (int k = 0; k < 16; ++k) {
            float a[8], b[8];
            *(float4*)(a)     = *(const float4*)&As[k][ty * 8];
            *(float4*)(a + 4) = *(const float4*)&As[k][ty * 8 + 4];
            *(float4*)(b)     = *(const float4*)&Bs[k][tx * 8];
            *(float4*)(b + 4) = *(const float4*)&Bs[k][tx * 8 + 4];
            #pragma unroll
            for (int i = 0; i < 8; ++i)
                #pragma unroll
                for (int j = 0; j < 8; ++j)
                    acc[i][j] = fmaf(a[i], b[j], acc[i][j]);
        }
        __syncthreads();
    }
    #pragma unroll
    for (int i = 0; i < 8; ++i) {
        size_t row = (size_t)(bm0 + ty * 8 + i);
        float* cp = C + row * N + bn0 + tx * 8;
        if (TANH) {
            #pragma unroll
            for (int j = 0; j < 8; ++j) acc[i][j] = tanhf(acc[i][j]);
        }
        *(float4*)(cp)     = make_float4(acc[i][0], acc[i][1], acc[i][2], acc[i][3]);
        *(float4*)(cp + 4) = make_float4(acc[i][4], acc[i][5], acc[i][6], acc[i][7]);
    }
}

// ----------------------- persistent RK4 scan kernel ------------------------
// 128 blocks, 1/SM (smem-limited, __launch_bounds__(256,1)).  Block owns a
// fixed (64 b-rows x 32 j-cols) output tile for the whole scan:
//   bm0 = (blockIdx.x & 7)*64, j0 = (blockIdx.x >> 3)*32.
// Weight slices for j0 chunk live in smem (3 x 512 x 32 f32 = 192 KB).
// Per-thread registers carry z, own-hs, h_base, kacc, Lx slice, dt across
// stages (ownership never moves).  Global exchange only for hs / rh (GEMM
// inputs span all j) -> __ldcg (L2) loads: L1 is NOT flushed inside a
// persistent kernel, plain ld.ca would read stale lines.
__global__ __launch_bounds__(256, 1)
void scan_kernel(const float* __restrict__ seq,
                 const float* __restrict__ Wg,
                 const float* __restrict__ Wlin,
                 const float* __restrict__ bg,
                 const float* __restrict__ blin,
                 const float* __restrict__ state0) {
    extern __shared__ float smf[];
    float* sWz = smf;                  // [512][32]
    float* sWr = smf + KS * 32;        // [512][32]
    float* sWl = smf + 2 * KS * 32;    // [512][32]
    float* Asb = smf + 3 * KS * 32;    // [2][16*68] double-buffered A tile

    const int tid = threadIdx.x;
    const int tn  = tid & 31;                 // j within chunk
    const int tm  = tid >> 5;                 // 0..7 -> 8 batch rows each
    const int bm0 = (blockIdx.x & 7) * 64;
    const int j0  = (blockIdx.x >> 3) * 32;
    const int lm  = tid >> 2;                 // 0..63  (A-tile loader row)
    const int lk4 = (tid & 3) * 4;            // 0,4,8,12

    // ---- load weight slices into smem (one-time) ----
    for (int u = tid; u < 32 * 128; u += 256) {
        int jj = u >> 7;                      // 0..31
        int kq = (u & 127) * 4;               // 0..508 step 4
        float4 v0 = *(const float4*)&Wg[(size_t)(j0 + jj) * KS + kq];
        float4 v1 = *(const float4*)&Wg[(size_t)(512 + j0 + jj) * KS + kq];
        float4 v2 = *(const float4*)&Wlin[(size_t)(j0 + jj) * KS + kq];
        sWz[(kq + 0) * 32 + jj] = v0.x; sWz[(kq + 1) * 32 + jj] = v0.y;
        sWz[(kq + 2) * 32 + jj] = v0.z; sWz[(kq + 3) * 32 + jj] = v0.w;
        sWr[(kq + 0) * 32 + jj] = v1.x; sWr[(kq + 1) * 32 + jj] = v1.y;
        sWr[(kq + 2) * 32 + jj] = v1.z; sWr[(kq + 3) * 32 + jj] = v1.w;
        sWl[(kq + 0) * 32 + jj] = v2.x; sWl[(kq + 1) * 32 + jj] = v2.y;
        sWl[(kq + 2) * 32 + jj] = v2.z; sWl[(kq + 3) * 32 + jj] = v2.w;
    }

    const int j = j0 + tn;
    const float bgz = bg[j];
    const float bgr = bg[512 + j];
    const float blv = blin[j];

    float hsv[8], hbv[8], kacc[8], zg[8];
    {
        float s0v = state0[j];
        #pragma unroll
        for (int i = 0; i < 8; ++i) { hsv[i] = s0v; hbv[i] = s0v; }
    }
    __syncthreads();

    int rp = 0;
    for (int t = 0; t < LSEQ; ++t) {
        float dtv[8], lz[8], lr[8], ll[8];
        #pragma unroll
        for (int i = 0; i < 8; ++i) {
            int b = bm0 + tm * 8 + i;
            dtv[i] = (t == 0) ? 0.f : seq[((size_t)(t - 1) * BDIM + b) * 16 + 15];
            size_t ro = ((size_t)t * BDIM + b) * NWX;
            lz[i] = g_Lx[ro + j];
            lr[i] = g_Lx[ro + 512 + j];
            ll[i] = g_Lx[ro + 1024 + j];
        }

        for (int st = 0; st < 4; ++st) {
            const float* hs = g_hsbuf[rp];

            // ---------- GEMM A: az/aq = hs @ [Wg_z; Wg_r]^T ----------
            float az[8], aq[8];
            #pragma unroll
            for (int i = 0; i < 8; ++i) { az[i] = 0.f; aq[i] = 0.f; }
            {
                float4 av = __ldcg((const float4*)&hs[(size_t)(bm0 + lm) * KS + lk4]);
                Asb[(lk4 + 0) * 68 + lm] = av.x; Asb[(lk4 + 1) * 68 + lm] = av.y;
                Asb[(lk4 + 2) * 68 + lm] = av.z; Asb[(lk4 + 3) * 68 + lm] = av.w;
                for (int k0 = 0; k0 < KS; k0 += 16) {
                    __syncthreads();
                    float4 nv;
                    const bool more = (k0 + 16 < KS);
                    if (more)
                        nv = __ldcg((const float4*)&hs[(size_t)(bm0 + lm) * KS + k0 + 16 + lk4]);
                    const float* Ac = Asb + ((k0 >> 4) & 1) * (16 * 68);
                    #pragma unroll
                    for (int k = 0; k < 16; ++k) {
                        float a[8];
                        *(float4*)(a)     = *(const float4*)(Ac + k * 68 + tm * 8);
                        *(float4*)(a + 4) = *(const float4*)(Ac + k * 68 + tm * 8 + 4);
                        float bz = sWz[(k0 + k) * 32 + tn];
                        float br = sWr[(k0 + k) * 32 + tn];
                        #pragma unroll
                        for (int i = 0; i < 8; ++i) {
                            az[i] = fmaf(a[i], bz, az[i]);
                            aq[i] = fmaf(a[i], br, aq[i]);
                        }
                    }
                    if (more) {
                        float* An = Asb + ((((k0 >> 4) & 1) ^ 1)) * (16 * 68);
                        An[(lk4 + 0) * 68 + lm] = nv.x; An[(lk4 + 1) * 68 + lm] = nv.y;
                        An[(lk4 + 2) * 68 + lm] = nv.z; An[(lk4 + 3) * 68 + lm] = nv.w;
                    }
                }
            }
            // gates epilogue: z stays in regs, rh exchanged via global
            #pragma unroll
            for (int i = 0; i < 8; ++i) {
                int b = bm0 + tm * 8 + i;
                zg[i] = sigmoidf_(az[i] + lz[i] + bgz);
                float rg = sigmoidf_(aq[i] + lr[i] + bgr);
                g_rh[b * KS + j] = rg * hsv[i];
            }
            grid_barrier();

            // ---------- GEMM B: al = rh @ Wlin^T ----------
            float al[8];
            #pragma unroll
            for (int i = 0; i < 8; ++i) al[i] = 0.f;
            {
                float4 av = __ldcg((const float4*)&g_rh[(size_t)(bm0 + lm) * KS + lk4]);
                Asb[(lk4 + 0) * 68 + lm] = av.x; Asb[(lk4 + 1) * 68 + lm] = av.y;
                Asb[(lk4 + 2) * 68 + lm] = av.z; Asb[(lk4 + 3) * 68 + lm] = av.w;
                for (int k0 = 0; k0 < KS; k0 += 16) {
                    __syncthreads();
                    float4 nv;
                    const bool more = (k0 + 16 < KS);
                    if (more)
                        nv = __ldcg((const float4*)&g_rh[(size_t)(bm0 + lm) * KS + k0 + 16 + lk4]);
                    const float* Ac = Asb + ((k0 >> 4) & 1) * (16 * 68);
                    #pragma unroll
                    for (int k = 0; k < 16; ++k) {
                        float a[8];
                        *(float4*)(a)     = *(const float4*)(Ac + k * 68 + tm * 8);
                        *(float4*)(a + 4) = *(const float4*)(Ac + k * 68 + tm * 8 + 4);
                        float bl = sWl[(k0 + k) * 32 + tn];
                        #pragma unroll
                        for (int i = 0; i < 8; ++i)
                            al[i] = fmaf(a[i], bl, al[i]);
                    }
                    if (more) {
                        float* An = Asb + ((((k0 >> 4) & 1) ^ 1)) * (16 * 68);
                        An[(lk4 + 0) * 68 + lm] = nv.x; An[(lk4 + 1) * 68 + lm] = nv.y;
                        An[(lk4 + 2) * 68 + lm] = nv.z; An[(lk4 + 3) * 68 + lm] = nv.w;
                    }
                }
            }
            // lin epilogue + RK4 update (all per-thread-owned state in regs)
            float* hsw = g_hsbuf[rp ^ 1];
            #pragma unroll
            for (int i = 0; i < 8; ++i) {
                int b = bm0 + tm * 8 + i;
                float kv = zg[i] * (tanhf(ll[i] + al[i] + blv) - hsv[i]);
                if (st == 0) {
                    kacc[i] = kv;
                    hsv[i] = hbv[i] + 0.5f * dtv[i] * kv;
                } else if (st == 1) {
                    kacc[i] += 2.f * kv;
                    hsv[i] = hbv[i] + 0.5f * dtv[i] * kv;
                } else if (st == 2) {
                    kacc[i] += 2.f * kv;
                    hsv[i] = hbv[i] + dtv[i] * kv;
                } else {
                    float hn = hbv[i] + dtv[i] * (kacc[i] + kv) * (1.f / 6.f);
                    hsv[i] = hn;
                    hbv[i] = hn;
                    g_states[((size_t)t * BDIM + b) * KS + j] = hn;
                }
                hsw[b * KS + j] = hsv[i];
            }
            rp ^= 1;
            grid_barrier();
        }
    }
}

// ---------------- y = T @ Ly2^T  -> out rows 1..255 ------------------------
__global__ __launch_bounds__(256)
void y_kernel(const float* __restrict__ Ly2, float* __restrict__ out) {
    __shared__ float sL[KOUT][KS];    // 16 KB
    for (int u = threadIdx.x; u < KOUT * KS; u += 256)
        sL[u >> 9][u & 511] = Ly2[u];
    __syncthreads();
    int w = threadIdx.x >> 5, lane = threadIdx.x & 31;
    int row = blockIdx.x * 8 + w;     // 0 .. 130559
    const float* tr = g_xe + (size_t)row * KS;
    float acc[KOUT] = {0.f, 0.f, 0.f, 0.f, 0.f, 0.f, 0.f, 0.f};
    #pragma unroll
    for (int c = 0; c < 4; ++c) {
        float4 v = *(const float4*)&tr[c * 128 + lane * 4];
        #pragma unroll
        for (int o = 0; o < KOUT; ++o) {
            float4 lv = *(const float4*)&sL[o][c * 128 + lane * 4];
            acc[o] += v.x * lv.x + v.y * lv.y + v.z * lv.z + v.w * lv.w;
        }
    }
    #pragma unroll
    for (int o = 0; o < KOUT; ++o)
        #pragma unroll
        for (int sh = 16; sh; sh >>= 1)
            acc[o] += __shfl_xor_sync(0xffffffffu, acc[o], sh);
    if (lane == 0) {
        int t = row >> 9, b = row & 511;
        float* op = out + ((size_t)((t + 1) << 9) + b) * KOUT;
        *(float4*)(op)     = make_float4(acc[0], acc[1], acc[2], acc[3]);
        *(float4*)(op + 4) = make_float4(acc[4], acc[5], acc[6], acc[7]);
    }
}

// ------------------------------- launcher ----------------------------------
extern "C" void kernel_launch(void* const* d_in, const int* in_sizes, int n_in,
                              void* d_out, int out_size) {
    const float* seq    = (const float*)d_in[0];
    const float* state0 = (const float*)d_in[1];
    const float* Win    = (const float*)d_in[2];
    const float* bin    = (const float*)d_in[3];
    const float* Wx     = (const float*)d_in[4];
    const float* Wg     = (const float*)d_in[5];
    const float* bg     = (const float*)d_in[6];
    const float* Wlin   = (const float*)d_in[7];
    const float* blin   = (const float*)d_in[8];
    const float* Ly1    = (const float*)d_in[9];
    const float* Ly2    = (const float*)d_in[10];
    float* out = (float*)d_out;

    float *p_xe = nullptr, *p_Lx = nullptr, *p_states = nullptr;
    cudaGetSymbolAddress((void**)&p_xe,     g_xe);
    cudaGetSymbolAddress((void**)&p_Lx,     g_Lx);
    cudaGetSymbolAddress((void**)&p_states, g_states);

    // scan kernel smem: 3*512*32 f32 weights + 2*16*68 f32 A-tiles = 205,312 B
    const int scan_smem = 3 * KS * 32 * 4 + 2 * 16 * 68 * 4;
    cudaFuncSetAttribute(scan_kernel,
                         cudaFuncAttributeMaxDynamicSharedMemorySize, scan_smem);

    // Phase 0: init state buffer + output row 0
    init_kernel<<<(BDIM * KS) / 256, 256>>>(state0);
    y0_kernel<<<1, 512>>>(state0, Ly1, Ly2, out);

    // Phase 1: xe
    xe_kernel<<<LB / 4, 256>>>(seq, Win, bin);

    // Phase 2: Lx = xe @ Wx^T   (131072 x 1536 x 512)
    sgemm_nt<false><<<dim3(NWX / 128, LB / 128), 256>>>(p_xe, Wx, p_Lx, LB, NWX, KS);

    // Phase 3: persistent RK4 scan (single launch, 2048 internal barriers)
    scan_kernel<<<NB, 256, scan_smem>>>(seq, Wg, Wlin, bg, blin, state0);

    // Phase 4: output head over states[0..254] (states[255] unused by y[:-1])
    const int MT = (LSEQ - 1) * BDIM;   // 130560, divisible by 128
    sgemm_nt<true><<<dim3(KS / 128, MT / 128), 256>>>(p_states, Ly1, p_xe, MT, KS, KS);
    y_kernel<<<MT / 8, 256>>>(Ly2, out);
}